// round 8
// baseline (speedup 1.0000x reference)
#include <cuda_runtime.h>
#include <math.h>

#define BSZ 32
#define LL 4096
#define HH 512
#define PP 384
#define VV 32
#define TOUT 16
#define NC 48
#define CHUNK 85           // (LL - TOUT) / NC = 4080/48
#define RR (BSZ*TOUT)      // 512 output rows
#define KXC (2*PP)         // 768
#define SK 16              // split-K factor

typedef unsigned long long u64;

// ---------------- scratch (device globals) ----------------
__device__ __align__(16) float2 d_Lbar[PP];
__device__ __align__(16) float2 d_Wpow[NC*PP];
__device__ __align__(16) float  d_BgRe[VV*PP];
__device__ __align__(16) float  d_BgIm[VV*PP];
__device__ __align__(16) float  d_xpartRe[BSZ*NC*PP];
__device__ __align__(16) float  d_xpartIm[BSZ*NC*PP];
__device__ __align__(16) float  d_Xbig[RR*KXC];     // [r][768] = [2xr | -2xi]
__device__ __align__(16) float  d_Cbig[KXC*HH];     // [768][512] = [Cre^T ; Cim^T]
__device__ __align__(16) float  d_y[RR*HH];
__device__ __align__(16) float  d_h1[RR*HH];
__device__ __align__(16) float  d_W2t[VV*HH];
__device__ __align__(16) float  d_part[SK*RR*HH];   // split-K partials (16 MB)

// ---------------- packed f32x2 helpers ----------------
__device__ __forceinline__ u64 pk2(float lo, float hi) {
    u64 r; asm("mov.b64 %0, {%1, %2};" : "=l"(r) : "f"(lo), "f"(hi)); return r;
}
__device__ __forceinline__ float2 upk(u64 x) {
    float lo, hi; asm("mov.b64 {%0, %1}, %2;" : "=f"(lo), "=f"(hi) : "l"(x));
    return make_float2(lo, hi);
}
__device__ __forceinline__ u64 fma2(u64 a, u64 b, u64 c) {
    u64 d; asm("fma.rn.f32x2 %0, %1, %2, %3;" : "=l"(d) : "l"(a), "l"(b), "l"(c));
    return d;
}

// ================= K1: all preprocessing =================
__global__ void __launch_bounds__(256) prep_all(
    const float* __restrict__ Lre, const float* __restrict__ Lim,
    const float* __restrict__ logstep,
    const float* __restrict__ embed, const float* __restrict__ Bre,
    const float* __restrict__ Bim, const float* __restrict__ W2,
    const float* __restrict__ Cre, const float* __restrict__ Cim)
{
    int bid = blockIdx.x, tid = threadIdx.x;
    if (bid >= PP + 16) {                       // build Cbig[k][h]
        int k = bid - (PP + 16);                // 0..767
        const float* src = (k < PP) ? Cre : Cim;
        int kk = (k < PP) ? k : k - PP;
        for (int h = tid; h < HH; h += 256)
            d_Cbig[k*HH + h] = src[(size_t)h*PP + kk];
        return;
    }
    if (bid >= PP) {                            // transpose W2
        int i = bid - PP;
        for (int e = i*1024 + tid; e < (i+1)*1024; e += 256) {
            int h = e >> 5, v = e & 31;
            d_W2t[v*HH + h] = W2[e];
        }
        return;
    }
    int p = bid;
    __shared__ float sBr[HH], sBi[HH];
    __shared__ float2 sg;
    for (int h = tid; h < HH; h += 256) {
        sBr[h] = Bre[p*HH + h];
        sBi[h] = Bim[p*HH + h];
    }
    if (tid < NC) {
        float lre = Lre[p], lim = Lim[p];
        float step = (float)exp((double)logstep[p]);
        float zr = lre * step, zi = lim * step;
        double m = exp((double)zr);
        double sv, cv; sincos((double)zi, &sv, &cv);
        float br = (float)(m * cv), bi = (float)(m * sv);
        if (tid == 0) {
            d_Lbar[p] = make_float2(br, bi);
            float ar = br - 1.f, ai = bi;
            float den = lre*lre + lim*lim;
            sg = make_float2((ar*lre + ai*lim)/den, (ai*lre - ar*lim)/den);
        }
        double dbr = (double)br, dbi = (double)bi;
        double lr = log(sqrt(dbr*dbr + dbi*dbi));
        double th = atan2(dbi, dbr);
        double e  = (double)(CHUNK * tid);
        double mm = exp(lr * e);
        double s2, c2; sincos(th * e, &s2, &c2);
        d_Wpow[tid*PP + p] = make_float2((float)(mm*c2), (float)(mm*s2));
    }
    __syncthreads();
    int warp = tid >> 5, lane = tid & 31;
    float2 g = sg;
    for (int v = warp; v < VV; v += 8) {
        float sr = 0.f, si = 0.f;
        for (int h = lane; h < HH; h += 32) {
            float e = embed[v*HH + h];
            sr = fmaf(e, sBr[h], sr);
            si = fmaf(e, sBi[h], si);
        }
        #pragma unroll
        for (int o = 16; o; o >>= 1) {
            sr += __shfl_xor_sync(0xffffffffu, sr, o);
            si += __shfl_xor_sync(0xffffffffu, si, o);
        }
        if (lane == 0) {
            d_BgRe[v*PP + p] = g.x*sr - g.y*si;
            d_BgIm[v*PP + p] = g.x*si + g.y*sr;
        }
    }
}

// ================= K2: chunked scan, SoA, 4 modes/thread =================
__global__ void __launch_bounds__(96) scan_chunks(const int* __restrict__ tokens) {
    __shared__ int stok[CHUNK];
    int b = blockIdx.y, c = blockIdx.x, t = threadIdx.x;
    if (t < CHUNK) stok[t] = tokens[b*LL + c*CHUNK + t];
    __syncthreads();
    int p0 = t * 4;
    float2 L0 = d_Lbar[p0+0], L1 = d_Lbar[p0+1];
    float2 L2 = d_Lbar[p0+2], L3 = d_Lbar[p0+3];
    u64 LrA = pk2(L0.x, L1.x), LrB = pk2(L2.x, L3.x);
    u64 LiA = pk2(L0.y, L1.y), LiB = pk2(L2.y, L3.y);
    u64 nLiA = pk2(-L0.y, -L1.y), nLiB = pk2(-L2.y, -L3.y);
    u64 XR0 = 0ull, XR1 = 0ull, XI0 = 0ull, XI1 = 0ull;
    const float* bgr = d_BgRe + p0;
    const float* bgi = d_BgIm + p0;
    #pragma unroll 5
    for (int i = 0; i < CHUNK; ++i) {
        int off = stok[i] * PP;
        ulonglong2 br = *(const ulonglong2*)(bgr + off);
        ulonglong2 bi = *(const ulonglong2*)(bgi + off);
        u64 nR0 = fma2(LrA, XR0, fma2(nLiA, XI0, br.x));
        u64 nI0 = fma2(LrA, XI0, fma2(LiA,  XR0, bi.x));
        u64 nR1 = fma2(LrB, XR1, fma2(nLiB, XI1, br.y));
        u64 nI1 = fma2(LrB, XI1, fma2(LiB,  XR1, bi.y));
        XR0 = nR0; XI0 = nI0; XR1 = nR1; XI1 = nI1;
    }
    int base = (b*NC + c)*PP + p0;
    *(ulonglong2*)(d_xpartRe + base) = make_ulonglong2(XR0, XR1);
    *(ulonglong2*)(d_xpartIm + base) = make_ulonglong2(XI0, XI1);
}

// ================= K3: combine chunks + 16 emission steps =================
__global__ void __launch_bounds__(192) combine_emit(const int* __restrict__ tokens) {
    int b = blockIdx.x;
    int p = blockIdx.y * 192 + threadIdx.x;
    float2 Lb = d_Lbar[p];
    float xr = 0.f, xi = 0.f;
    #pragma unroll 8
    for (int c = 0; c < NC; ++c) {
        float2 W = d_Wpow[(NC - 1 - c)*PP + p];
        int base = (b*NC + c)*PP + p;
        float pr = d_xpartRe[base], pi = d_xpartIm[base];
        xr = fmaf(W.x, pr, fmaf(-W.y, pi, xr));
        xi = fmaf(W.x, pi, fmaf( W.y, pr, xi));
    }
    int tk[TOUT];
    #pragma unroll
    for (int j = 0; j < TOUT; ++j) tk[j] = tokens[b*LL + (LL - TOUT) + j];
    #pragma unroll
    for (int j = 0; j < TOUT; ++j) {
        float bgr = d_BgRe[tk[j]*PP + p];
        float bgi = d_BgIm[tk[j]*PP + p];
        float nr = fmaf(Lb.x, xr, fmaf(-Lb.y, xi, bgr));
        float ni = fmaf(Lb.y, xr, fmaf( Lb.x, xi, bgi));
        xr = nr; xi = ni;
        int r = b*TOUT + j;
        d_Xbig[r*KXC + p]      =  2.f * xr;
        d_Xbig[r*KXC + PP + p] = -2.f * xi;
    }
}

// ===== split-K GEMM: 64x128 tile, 128 thr (4 warps), warp = 16 rows x 128 cols =====
__global__ void __launch_bounds__(128) gemm_sk(const float* __restrict__ A,
                                               const float* __restrict__ B,
                                               int Ktot) {
    __shared__ __align__(16) u64   sA[16][66];    // 64 A-rows dup-packed, padded
    __shared__ __align__(16) float sB[16][132];   // 128 B-cols, padded
    int tid  = threadIdx.x;
    int warp = tid >> 5, lane = tid & 31;
    int row0 = blockIdx.y * 64, col0 = blockIdx.x * 128;
    int Kc = Ktot / SK;
    int k0 = blockIdx.z * Kc;
    u64 acc[16][2];
    #pragma unroll
    for (int i = 0; i < 16; ++i) { acc[i][0] = 0ull; acc[i][1] = 0ull; }

    int arow = tid & 63, akq = tid >> 6;
    for (int kk = 0; kk < Kc; kk += 16) {
        #pragma unroll
        for (int q = 0; q < 2; ++q) {
            float4 v = *(const float4*)(A + (size_t)(row0 + arow)*Ktot + k0 + kk
                                          + (akq*2 + q)*4);
            int kb = (akq*2 + q)*4;
            sA[kb+0][arow] = pk2(v.x, v.x);
            sA[kb+1][arow] = pk2(v.y, v.y);
            sA[kb+2][arow] = pk2(v.z, v.z);
            sA[kb+3][arow] = pk2(v.w, v.w);
        }
        #pragma unroll
        for (int it = 0; it < 4; ++it) {          // B: 16k x 128 cols
            int idx = tid + it*128;               // 0..511
            int kr = idx >> 5, cb = (idx & 31) * 4;
            *(float4*)&sB[kr][cb] =
                *(const float4*)(B + (size_t)(k0 + kk + kr)*HH + col0 + cb);
        }
        __syncthreads();
        #pragma unroll
        for (int k = 0; k < 16; ++k) {
            u64 bb[2];
            *(ulonglong2*)&bb[0] = *(const ulonglong2*)&sB[k][lane*4];
            const u64* ap = &sA[k][warp*16];      // warp-uniform -> broadcast
            #pragma unroll
            for (int i = 0; i < 8; ++i) {
                ulonglong2 av = *(const ulonglong2*)(ap + 2*i);
                acc[2*i+0][0] = fma2(av.x, bb[0], acc[2*i+0][0]);
                acc[2*i+0][1] = fma2(av.x, bb[1], acc[2*i+0][1]);
                acc[2*i+1][0] = fma2(av.y, bb[0], acc[2*i+1][0]);
                acc[2*i+1][1] = fma2(av.y, bb[1], acc[2*i+1][1]);
            }
        }
        __syncthreads();
    }
    float* out = d_part + (size_t)blockIdx.z * (RR*HH);
    #pragma unroll
    for (int i = 0; i < 16; ++i) {
        float2 f0 = upk(acc[i][0]), f1 = upk(acc[i][1]);
        *(float4*)(out + (size_t)(row0 + warp*16 + i)*HH + col0 + lane*4)
            = make_float4(f0.x, f0.y, f1.x, f1.y);
    }
}

// ================= reduces (vectorized, fused epilogues) =================
__global__ void __launch_bounds__(256) reduce_y(const int* __restrict__ tokens,
                                                const float* __restrict__ embed,
                                                const float* __restrict__ D) {
    int idx = blockIdx.x*256 + threadIdx.x;      // RR*HH/4 items
    int i4 = idx * 4;
    int r = i4 >> 9, h = i4 & 511;
    int tok = tokens[(r >> 4)*LL + (LL - TOUT) + (r & 15)];
    float4 u  = *(const float4*)(embed + (size_t)tok*HH + h);
    float4 dv = *(const float4*)(D + h);
    float4 s = make_float4(u.x*dv.x, u.y*dv.y, u.z*dv.z, u.w*dv.w);
    #pragma unroll
    for (int z = 0; z < SK; ++z) {
        float4 p = *(const float4*)(d_part + (size_t)z*RR*HH + i4);
        s.x += p.x; s.y += p.y; s.z += p.z; s.w += p.w;
    }
    *(float4*)(d_y + i4) = s;
}
__global__ void __launch_bounds__(256) reduce_h1(const float* __restrict__ b1) {
    int idx = blockIdx.x*256 + threadIdx.x;
    int i4 = idx * 4;
    int h = i4 & 511;
    float4 s = *(const float4*)(b1 + h);
    #pragma unroll
    for (int z = 0; z < SK; ++z) {
        float4 p = *(const float4*)(d_part + (size_t)z*RR*HH + i4);
        s.x += p.x; s.y += p.y; s.z += p.z; s.w += p.w;
    }
    s.x = fmaxf(s.x, 0.f); s.y = fmaxf(s.y, 0.f);
    s.z = fmaxf(s.z, 0.f); s.w = fmaxf(s.w, 0.f);
    *(float4*)(d_h1 + i4) = s;
}

// ================= final: out = h1 @ W2 + b2 (W2t) =================
__global__ void __launch_bounds__(256) final_out(const float* __restrict__ b2,
                                                 float* __restrict__ out) {
    int idx = blockIdx.x*256 + threadIdx.x;      // RR*VV
    int r = idx >> 5, v = idx & 31;
    const float* hrow = d_h1 + (size_t)r*HH;
    const float* wrow = d_W2t + (size_t)v*HH;
    u64 a = 0ull, b = 0ull;
    #pragma unroll 8
    for (int h = 0; h < HH; h += 4) {
        ulonglong2 hv = *(const ulonglong2*)(hrow + h);
        ulonglong2 wv = *(const ulonglong2*)(wrow + h);
        a = fma2(hv.x, wv.x, a);
        b = fma2(hv.y, wv.y, b);
    }
    float2 fa = upk(a), fb = upk(b);
    out[idx] = fa.x + fa.y + fb.x + fb.y + b2[v];
}

// ================= launcher =================
extern "C" void kernel_launch(void* const* d_in, const int* in_sizes, int n_in,
                              void* d_out, int out_size) {
    const int*   tokens  = (const int*)  d_in[0];
    const float* embed   = (const float*)d_in[1];
    const float* Lre     = (const float*)d_in[2];
    const float* Lim     = (const float*)d_in[3];
    const float* Bre     = (const float*)d_in[4];
    const float* Bim     = (const float*)d_in[5];
    const float* Cre     = (const float*)d_in[6];
    const float* Cim     = (const float*)d_in[7];
    const float* D       = (const float*)d_in[8];
    const float* logstep = (const float*)d_in[9];
    const float* W1      = (const float*)d_in[10];
    const float* b1      = (const float*)d_in[11];
    const float* W2      = (const float*)d_in[12];
    const float* b2      = (const float*)d_in[13];
    float* out = (float*)d_out;

    float *xbig_p, *cbig_p, *y_p;
    cudaGetSymbolAddress((void**)&xbig_p, d_Xbig);
    cudaGetSymbolAddress((void**)&cbig_p, d_Cbig);
    cudaGetSymbolAddress((void**)&y_p,    d_y);

    prep_all<<<PP + 16 + KXC, 256>>>(Lre, Lim, logstep, embed, Bre, Bim, W2, Cre, Cim);
    scan_chunks<<<dim3(NC, BSZ), 96>>>(tokens);
    combine_emit<<<dim3(BSZ, 2), 192>>>(tokens);
    gemm_sk<<<dim3(4, 8, SK), 128>>>(xbig_p, cbig_p, KXC);   // y partials
    reduce_y<<<(RR*HH/4)/256, 256>>>(tokens, embed, D);
    gemm_sk<<<dim3(4, 8, SK), 128>>>(y_p, W1, HH);           // h1 partials
    reduce_h1<<<(RR*HH/4)/256, 256>>>(b1);
    final_out<<<(RR*VV)/256, 256>>>(b2, out);
}

// round 9
// speedup vs baseline: 1.2643x; 1.2643x over previous
#include <cuda_runtime.h>
#include <math.h>

#define BSZ 32
#define LL 4096
#define HH 512
#define PP 384
#define VV 32
#define TOUT 16
#define NC 16
#define CHUNK 255          // (LL - TOUT) / NC
#define RR (BSZ*TOUT)      // 512 output rows
#define KXC (2*PP)         // 768
#define SK 8               // split-K factor

typedef unsigned long long u64;

// ---------------- scratch (device globals) ----------------
__device__ __align__(16) float2 d_Lbar[PP];
__device__ __align__(16) float2 d_Wpow[NC*PP];
__device__ __align__(16) float  d_BgRe[VV*PP];
__device__ __align__(16) float  d_BgIm[VV*PP];
__device__ __align__(16) float  d_xpartRe[BSZ*NC*PP];
__device__ __align__(16) float  d_xpartIm[BSZ*NC*PP];
__device__ __align__(16) float  d_Xbig[RR*KXC];     // [r][768] = [2xr | -2xi]
__device__ __align__(16) float  d_Cbig[KXC*HH];     // [768][512] = [Cre^T ; Cim^T]
__device__ __align__(16) float  d_y[RR*HH];
__device__ __align__(16) float  d_W2t[VV*HH];
__device__ __align__(16) float  d_part[SK*RR*HH];   // split-K partials (8 MB)

// ---------------- packed f32x2 helpers ----------------
__device__ __forceinline__ u64 pk2(float lo, float hi) {
    u64 r; asm("mov.b64 %0, {%1, %2};" : "=l"(r) : "f"(lo), "f"(hi)); return r;
}
__device__ __forceinline__ float2 upk(u64 x) {
    float lo, hi; asm("mov.b64 {%0, %1}, %2;" : "=f"(lo), "=f"(hi) : "l"(x));
    return make_float2(lo, hi);
}
__device__ __forceinline__ u64 fma2(u64 a, u64 b, u64 c) {
    u64 d; asm("fma.rn.f32x2 %0, %1, %2, %3;" : "=l"(d) : "l"(a), "l"(b), "l"(c));
    return d;
}

// ================= K1: all preprocessing =================
// [0,PP): per-mode constants + Bg ; [PP,PP+16): W2t ; [PP+16,PP+16+384): Cbig transpose
__global__ void __launch_bounds__(256) prep_all(
    const float* __restrict__ Lre, const float* __restrict__ Lim,
    const float* __restrict__ logstep,
    const float* __restrict__ embed, const float* __restrict__ Bre,
    const float* __restrict__ Bim, const float* __restrict__ W2,
    const float* __restrict__ Cre, const float* __restrict__ Cim)
{
    int bid = blockIdx.x, tid = threadIdx.x;
    if (bid >= PP + 16) {                       // Cbig[k][h] via smem tile transpose
        __shared__ float ts[32][33];
        int m = bid - (PP + 16);                // 0..383 : 24 k-tiles x 16 h-tiles
        int ktile = m % 24, htile = m / 24;
        int k0 = ktile * 32, h0 = htile * 32;
        const float* src = (k0 < PP) ? Cre : Cim;
        int kk0 = (k0 < PP) ? k0 : k0 - PP;
        int j = tid & 31, i0 = tid >> 5;
        #pragma unroll
        for (int q = 0; q < 4; ++q) {
            int i = i0 + 8*q;
            ts[j][i] = src[(size_t)(h0 + i)*PP + kk0 + j];
        }
        __syncthreads();
        #pragma unroll
        for (int q = 0; q < 4; ++q) {
            int jk = i0 + 8*q;
            d_Cbig[(size_t)(k0 + jk)*HH + h0 + j] = ts[jk][j];
        }
        return;
    }
    if (bid >= PP) {                            // transpose W2
        int i = bid - PP;
        for (int e = i*1024 + tid; e < (i+1)*1024; e += 256) {
            int h = e >> 5, v = e & 31;
            d_W2t[v*HH + h] = W2[e];
        }
        return;
    }
    int p = bid;
    __shared__ float sBr[HH], sBi[HH];
    __shared__ float2 sg;
    for (int h = tid; h < HH; h += 256) {
        sBr[h] = Bre[p*HH + h];
        sBi[h] = Bim[p*HH + h];
    }
    if (tid < NC) {
        float lre = Lre[p], lim = Lim[p];
        float step = (float)exp((double)logstep[p]);
        float zr = lre * step, zi = lim * step;
        double m = exp((double)zr);
        double sv, cv; sincos((double)zi, &sv, &cv);
        float br = (float)(m * cv), bi = (float)(m * sv);
        if (tid == 0) {
            d_Lbar[p] = make_float2(br, bi);
            float ar = br - 1.f, ai = bi;
            float den = lre*lre + lim*lim;
            sg = make_float2((ar*lre + ai*lim)/den, (ai*lre - ar*lim)/den);
        }
        double dbr = (double)br, dbi = (double)bi;
        double lr = log(sqrt(dbr*dbr + dbi*dbi));
        double th = atan2(dbi, dbr);
        double e  = (double)(CHUNK * tid);
        double mm = exp(lr * e);
        double s2, c2; sincos(th * e, &s2, &c2);
        d_Wpow[tid*PP + p] = make_float2((float)(mm*c2), (float)(mm*s2));
    }
    __syncthreads();
    int warp = tid >> 5, lane = tid & 31;
    float2 g = sg;
    for (int v = warp; v < VV; v += 8) {
        float sr = 0.f, si = 0.f;
        for (int h = lane; h < HH; h += 32) {
            float e = embed[v*HH + h];
            sr = fmaf(e, sBr[h], sr);
            si = fmaf(e, sBi[h], si);
        }
        #pragma unroll
        for (int o = 16; o; o >>= 1) {
            sr += __shfl_xor_sync(0xffffffffu, sr, o);
            si += __shfl_xor_sync(0xffffffffu, si, o);
        }
        if (lane == 0) {
            d_BgRe[v*PP + p] = g.x*sr - g.y*si;
            d_BgIm[v*PP + p] = g.x*si + g.y*sr;
        }
    }
}

// ================= K2: chunked scan, SoA, 4 modes/thread =================
__global__ void __launch_bounds__(96) scan_chunks(const int* __restrict__ tokens) {
    __shared__ int stok[CHUNK];
    int b = blockIdx.y, c = blockIdx.x, t = threadIdx.x;
    for (int i = t; i < CHUNK; i += 96) stok[i] = tokens[b*LL + c*CHUNK + i];
    __syncthreads();
    int p0 = t * 4;
    float2 L0 = d_Lbar[p0+0], L1 = d_Lbar[p0+1];
    float2 L2 = d_Lbar[p0+2], L3 = d_Lbar[p0+3];
    u64 LrA = pk2(L0.x, L1.x), LrB = pk2(L2.x, L3.x);
    u64 LiA = pk2(L0.y, L1.y), LiB = pk2(L2.y, L3.y);
    u64 nLiA = pk2(-L0.y, -L1.y), nLiB = pk2(-L2.y, -L3.y);
    u64 XR0 = 0ull, XR1 = 0ull, XI0 = 0ull, XI1 = 0ull;
    const float* bgr = d_BgRe + p0;
    const float* bgi = d_BgIm + p0;
    #pragma unroll 5
    for (int i = 0; i < CHUNK; ++i) {
        int off = stok[i] * PP;
        ulonglong2 br = *(const ulonglong2*)(bgr + off);
        ulonglong2 bi = *(const ulonglong2*)(bgi + off);
        u64 nR0 = fma2(LrA, XR0, fma2(nLiA, XI0, br.x));
        u64 nI0 = fma2(LrA, XI0, fma2(LiA,  XR0, bi.x));
        u64 nR1 = fma2(LrB, XR1, fma2(nLiB, XI1, br.y));
        u64 nI1 = fma2(LrB, XI1, fma2(LiB,  XR1, bi.y));
        XR0 = nR0; XI0 = nI0; XR1 = nR1; XI1 = nI1;
    }
    int base = (b*NC + c)*PP + p0;
    *(ulonglong2*)(d_xpartRe + base) = make_ulonglong2(XR0, XR1);
    *(ulonglong2*)(d_xpartIm + base) = make_ulonglong2(XI0, XI1);
}

// ================= K3: combine chunks + 16 emission steps =================
__global__ void __launch_bounds__(192) combine_emit(const int* __restrict__ tokens) {
    int b = blockIdx.x;
    int p = blockIdx.y * 192 + threadIdx.x;
    float2 Lb = d_Lbar[p];
    float xr = 0.f, xi = 0.f;
    #pragma unroll
    for (int c = 0; c < NC; ++c) {
        float2 W = d_Wpow[(NC - 1 - c)*PP + p];
        int base = (b*NC + c)*PP + p;
        float pr = d_xpartRe[base], pi = d_xpartIm[base];
        xr = fmaf(W.x, pr, fmaf(-W.y, pi, xr));
        xi = fmaf(W.x, pi, fmaf( W.y, pr, xi));
    }
    int tk[TOUT];
    #pragma unroll
    for (int j = 0; j < TOUT; ++j) tk[j] = tokens[b*LL + (LL - TOUT) + j];
    #pragma unroll
    for (int j = 0; j < TOUT; ++j) {
        float bgr = d_BgRe[tk[j]*PP + p];
        float bgi = d_BgIm[tk[j]*PP + p];
        float nr = fmaf(Lb.x, xr, fmaf(-Lb.y, xi, bgr));
        float ni = fmaf(Lb.y, xr, fmaf( Lb.x, xi, bgi));
        xr = nr; xi = ni;
        int r = b*TOUT + j;
        d_Xbig[r*KXC + p]      =  2.f * xr;
        d_Xbig[r*KXC + PP + p] = -2.f * xi;
    }
}

// ===== split-K GEMM: 64x128 tile, 128 thr, double-buffered smem + reg prefetch =====
__global__ void __launch_bounds__(128) gemm_sk(const float* __restrict__ A,
                                               const float* __restrict__ B,
                                               int Ktot) {
    __shared__ __align__(16) u64   sA[2][16][66];
    __shared__ __align__(16) float sB[2][16][132];
    int tid  = threadIdx.x;
    int warp = tid >> 5, lane = tid & 31;
    int row0 = blockIdx.y * 64, col0 = blockIdx.x * 128;
    int Kc = Ktot / SK;
    int k0 = blockIdx.z * Kc;
    int ntiles = Kc / 16;
    u64 acc[16][2];
    #pragma unroll
    for (int i = 0; i < 16; ++i) { acc[i][0] = 0ull; acc[i][1] = 0ull; }

    int arow = tid & 63, akq = tid >> 6;          // A: thread covers k-offsets akq*8+{0,4}
    const float* Abase = A + (size_t)(row0 + arow)*Ktot + k0 + akq*8;
    const float* Bbase = B + (size_t)(k0 + warp)*HH + col0 + lane*4;  // rows warp+4*it

    float4 av0, av1, bv[4];
    // prologue: load tile 0
    av0 = *(const float4*)(Abase);
    av1 = *(const float4*)(Abase + 4);
    #pragma unroll
    for (int it = 0; it < 4; ++it)
        bv[it] = *(const float4*)(Bbase + (size_t)(4*it)*HH);
    {   // STS tile 0 -> buf 0
        int kb = akq*8;
        sA[0][kb+0][arow] = pk2(av0.x, av0.x); sA[0][kb+1][arow] = pk2(av0.y, av0.y);
        sA[0][kb+2][arow] = pk2(av0.z, av0.z); sA[0][kb+3][arow] = pk2(av0.w, av0.w);
        sA[0][kb+4][arow] = pk2(av1.x, av1.x); sA[0][kb+5][arow] = pk2(av1.y, av1.y);
        sA[0][kb+6][arow] = pk2(av1.z, av1.z); sA[0][kb+7][arow] = pk2(av1.w, av1.w);
        #pragma unroll
        for (int it = 0; it < 4; ++it)
            *(float4*)&sB[0][warp + 4*it][lane*4] = bv[it];
    }
    __syncthreads();

    for (int t = 0; t < ntiles; ++t) {
        int cur = t & 1;
        if (t + 1 < ntiles) {                    // prefetch next tile into regs
            int kk = (t + 1) * 16;
            av0 = *(const float4*)(Abase + kk);
            av1 = *(const float4*)(Abase + kk + 4);
            #pragma unroll
            for (int it = 0; it < 4; ++it)
                bv[it] = *(const float4*)(Bbase + (size_t)(kk + 4*it)*HH);
        }
        #pragma unroll
        for (int k = 0; k < 16; ++k) {           // compute current tile
            u64 bb[2];
            *(ulonglong2*)&bb[0] = *(const ulonglong2*)&sB[cur][k][lane*4];
            const u64* ap = &sA[cur][k][warp*16];
            #pragma unroll
            for (int i = 0; i < 8; ++i) {
                ulonglong2 avv = *(const ulonglong2*)(ap + 2*i);
                acc[2*i+0][0] = fma2(avv.x, bb[0], acc[2*i+0][0]);
                acc[2*i+0][1] = fma2(avv.x, bb[1], acc[2*i+0][1]);
                acc[2*i+1][0] = fma2(avv.y, bb[0], acc[2*i+1][0]);
                acc[2*i+1][1] = fma2(avv.y, bb[1], acc[2*i+1][1]);
            }
        }
        if (t + 1 < ntiles) {                    // STS next tile into other buffer
            int nxt = cur ^ 1;
            int kb = akq*8;
            sA[nxt][kb+0][arow] = pk2(av0.x, av0.x); sA[nxt][kb+1][arow] = pk2(av0.y, av0.y);
            sA[nxt][kb+2][arow] = pk2(av0.z, av0.z); sA[nxt][kb+3][arow] = pk2(av0.w, av0.w);
            sA[nxt][kb+4][arow] = pk2(av1.x, av1.x); sA[nxt][kb+5][arow] = pk2(av1.y, av1.y);
            sA[nxt][kb+6][arow] = pk2(av1.z, av1.z); sA[nxt][kb+7][arow] = pk2(av1.w, av1.w);
            #pragma unroll
            for (int it = 0; it < 4; ++it)
                *(float4*)&sB[nxt][warp + 4*it][lane*4] = bv[it];
        }
        __syncthreads();
    }
    float* out = d_part + (size_t)blockIdx.z * (RR*HH);
    #pragma unroll
    for (int i = 0; i < 16; ++i) {
        float2 f0 = upk(acc[i][0]), f1 = upk(acc[i][1]);
        *(float4*)(out + (size_t)(row0 + warp*16 + i)*HH + col0 + lane*4)
            = make_float4(f0.x, f0.y, f1.x, f1.y);
    }
}

// ================= reduce_y (fused u*D epilogue) =================
__global__ void __launch_bounds__(256) reduce_y(const int* __restrict__ tokens,
                                                const float* __restrict__ embed,
                                                const float* __restrict__ D) {
    int idx = blockIdx.x*256 + threadIdx.x;      // RR*HH/4 items
    int i4 = idx * 4;
    int r = i4 >> 9, h = i4 & 511;
    int tok = tokens[(r >> 4)*LL + (LL - TOUT) + (r & 15)];
    float4 u  = *(const float4*)(embed + (size_t)tok*HH + h);
    float4 dv = *(const float4*)(D + h);
    float4 s = make_float4(u.x*dv.x, u.y*dv.y, u.z*dv.z, u.w*dv.w);
    #pragma unroll
    for (int z = 0; z < SK; ++z) {
        float4 p = *(const float4*)(d_part + (size_t)z*RR*HH + i4);
        s.x += p.x; s.y += p.y; s.z += p.z; s.w += p.w;
    }
    *(float4*)(d_y + i4) = s;
}

// ===== mlp_tail: h1 = relu(sum partials + b1) in smem, then out = h1@W2t + b2 =====
__global__ void __launch_bounds__(256) mlp_tail(const float* __restrict__ b1,
                                                const float* __restrict__ b2,
                                                float* __restrict__ out) {
    __shared__ __align__(16) float hs[4][HH];
    int tid = threadIdx.x;
    int r0 = blockIdx.x * 4;
    // phase 1: 4 rows x 512 = 2048 elems, 8 per thread
    int e = tid * 8, row = e >> 9, col = e & 511;
    int gi = (r0 + row)*HH + col;
    float4 s0 = *(const float4*)(b1 + col);
    float4 s1 = *(const float4*)(b1 + col + 4);
    #pragma unroll
    for (int z = 0; z < SK; ++z) {
        const float* pp = d_part + (size_t)z*RR*HH + gi;
        float4 p0 = *(const float4*)pp;
        float4 p1 = *(const float4*)(pp + 4);
        s0.x += p0.x; s0.y += p0.y; s0.z += p0.z; s0.w += p0.w;
        s1.x += p1.x; s1.y += p1.y; s1.z += p1.z; s1.w += p1.w;
    }
    s0.x = fmaxf(s0.x, 0.f); s0.y = fmaxf(s0.y, 0.f);
    s0.z = fmaxf(s0.z, 0.f); s0.w = fmaxf(s0.w, 0.f);
    s1.x = fmaxf(s1.x, 0.f); s1.y = fmaxf(s1.y, 0.f);
    s1.z = fmaxf(s1.z, 0.f); s1.w = fmaxf(s1.w, 0.f);
    *(float4*)&hs[row][col]     = s0;
    *(float4*)&hs[row][col + 4] = s1;
    __syncthreads();
    // phase 2: 128 threads = 4 rows x 32 vocab
    if (tid < 128) {
        int rw = tid >> 5, v = tid & 31;
        const float* wr = d_W2t + (size_t)v*HH;
        u64 a = 0ull, b = 0ull;
        #pragma unroll 8
        for (int h = 0; h < HH; h += 4) {
            ulonglong2 hv = *(const ulonglong2*)&hs[rw][h];
            ulonglong2 wv = *(const ulonglong2*)(wr + h);
            a = fma2(hv.x, wv.x, a);
            b = fma2(hv.y, wv.y, b);
        }
        float2 fa = upk(a), fb = upk(b);
        out[(r0 + rw)*VV + v] = fa.x + fa.y + fb.x + fb.y + b2[v];
    }
}

// ================= launcher =================
extern "C" void kernel_launch(void* const* d_in, const int* in_sizes, int n_in,
                              void* d_out, int out_size) {
    const int*   tokens  = (const int*)  d_in[0];
    const float* embed   = (const float*)d_in[1];
    const float* Lre     = (const float*)d_in[2];
    const float* Lim     = (const float*)d_in[3];
    const float* Bre     = (const float*)d_in[4];
    const float* Bim     = (const float*)d_in[5];
    const float* Cre     = (const float*)d_in[6];
    const float* Cim     = (const float*)d_in[7];
    const float* D       = (const float*)d_in[8];
    const float* logstep = (const float*)d_in[9];
    const float* W1      = (const float*)d_in[10];
    const float* b1      = (const float*)d_in[11];
    const float* W2      = (const float*)d_in[12];
    const float* b2      = (const float*)d_in[13];
    float* out = (float*)d_out;

    float *xbig_p, *cbig_p, *y_p;
    cudaGetSymbolAddress((void**)&xbig_p, d_Xbig);
    cudaGetSymbolAddress((void**)&cbig_p, d_Cbig);
    cudaGetSymbolAddress((void**)&y_p,    d_y);

    prep_all<<<PP + 16 + 384, 256>>>(Lre, Lim, logstep, embed, Bre, Bim, W2, Cre, Cim);
    scan_chunks<<<dim3(NC, BSZ), 96>>>(tokens);
    combine_emit<<<dim3(BSZ, 2), 192>>>(tokens);
    gemm_sk<<<dim3(4, 8, SK), 128>>>(xbig_p, cbig_p, KXC);   // y partials
    reduce_y<<<(RR*HH/4)/256, 256>>>(tokens, embed, D);
    gemm_sk<<<dim3(4, 8, SK), 128>>>(y_p, W1, HH);           // h1 partials
    mlp_tail<<<RR/4, 256>>>(b1, b2, out);
}